// round 6
// baseline (speedup 1.0000x reference)
#include <cuda_runtime.h>
#include <math.h>
#include <stdint.h>

#define N_NODES 4096
#define E_EDGES 131072
#define EN_EDGES (E_EDGES + N_NODES)
#define D_INP 128
#define D_MODEL 256
#define H_HEADS 8
#define D_HEAD 32
#define FF_DIM 2048
#define B_PAIRS 16384

// ---------------- scratch (device globals; allocation-free) ----------------
__device__ __align__(256) float g_h[N_NODES * D_MODEL];
__device__ __align__(256) float g_qkv[N_NODES * 3 * D_MODEL];
__device__ __align__(256) float g_ctx[N_NODES * D_MODEL];
__device__ __align__(256) float g_tmp[N_NODES * D_MODEL];
__device__ __align__(256) float g_h1[N_NODES * D_MODEL];
__device__ __align__(256) float g_ff[N_NODES * FF_DIM];
__device__ __align__(256) float g_h2[N_NODES * D_MODEL];
__device__ __align__(256) float g_hw[N_NODES * H_HEADS * D_MODEL];
__device__ __align__(256) float g_asrc[N_NODES * H_HEADS];
__device__ __align__(256) float g_adst[N_NODES * H_HEADS];
__device__ __align__(256) float g_hg[N_NODES * D_MODEL];
__device__ int g_deg[N_NODES];
__device__ int g_off[N_NODES + 1];
__device__ int g_cursor[N_NODES];
__device__ int g_csrc[EN_EDGES];

// ---------------- helpers ----------------
__device__ __forceinline__ void mma_tf32(float* d, const uint32_t* a,
                                         const uint32_t* b) {
  asm volatile(
      "mma.sync.aligned.m16n8k8.row.col.f32.tf32.tf32.f32 "
      "{%0,%1,%2,%3}, {%4,%5,%6,%7}, {%8,%9}, {%0,%1,%2,%3};\n"
      : "+f"(d[0]), "+f"(d[1]), "+f"(d[2]), "+f"(d[3])
      : "r"(a[0]), "r"(a[1]), "r"(a[2]), "r"(a[3]), "r"(b[0]), "r"(b[1]));
}
__device__ __forceinline__ void cp_async16(void* s, const void* g) {
  uint32_t sa = (uint32_t)__cvta_generic_to_shared(s);
  asm volatile("cp.async.cg.shared.global [%0], [%1], 16;" ::"r"(sa), "l"(g)
               : "memory");
}
__device__ __forceinline__ void cp_commit() {
  asm volatile("cp.async.commit_group;" ::: "memory");
}
template <int Nleft>
__device__ __forceinline__ void cp_wait() {
  asm volatile("cp.async.wait_group %0;" ::"n"(Nleft) : "memory");
}

// ---------------- TF32 tensor-core GEMM: C[M,N] = A[M,K] @ B[K,N] ----------
// Tile 64x64x16, 256 threads (8 warps: 2 M x 4 N), warp tile 32x16.
// 4-stage cp.async pipeline, ONE __syncthreads per k-iter.
// Requires K >= 48 and K % 16 == 0 (all call sites: K in {128,256,2048}).
template <int RELU>
__global__ __launch_bounds__(256) void mma_gemm(
    const float* __restrict__ A, const float* __restrict__ B,
    const float* __restrict__ bias, float* __restrict__ C,
    int M, int Nn, int K) {
  __shared__ float As[4][64][20];
  __shared__ float Bs[4][16][72];
  int tid = threadIdx.x;
  int warp = tid >> 5, lane = tid & 31;
  int gid = lane >> 2, tig = lane & 3;
  int bm = blockIdx.y * 64, bn = blockIdx.x * 64;
  int wm = (warp & 1) * 32;
  int wn = (warp >> 1) * 16;

  float acc[2][2][4];
#pragma unroll
  for (int t = 0; t < 2; t++)
#pragma unroll
    for (int u = 0; u < 2; u++)
#pragma unroll
      for (int i = 0; i < 4; i++) acc[t][u][i] = 0.f;

  int ar = tid >> 2, ac = (tid & 3) * 4;  // A: 64 rows x 16 cols, 1 f4/thread
  int br = tid >> 4, bc = (tid & 15) * 4; // B: 16 rows x 64 cols, 1 f4/thread
  const float* Aptr = A + (size_t)(bm + ar) * K + ac;
  const float* Bptr = B + (size_t)br * Nn + bn + bc;

#define GEMM_LOAD(s, k0)                                  \
  do {                                                    \
    cp_async16(&As[s][ar][ac], Aptr + (k0));              \
    cp_async16(&Bs[s][br][bc], Bptr + (size_t)(k0) * Nn); \
    cp_commit();                                          \
  } while (0)

  GEMM_LOAD(0, 0);
  GEMM_LOAD(1, 16);
  GEMM_LOAD(2, 32);

  int i = 0;
  for (int k0 = 0; k0 < K; k0 += 16, i++) {
    // need block i resident; blocks issued so far: up to i+2
    if (k0 + 32 < K) cp_wait<2>();
    else if (k0 + 16 < K) cp_wait<1>();
    else cp_wait<0>();
    __syncthreads();  // all warps past iter i-1; stage (i+3)&3 is free
    if (k0 + 48 < K) GEMM_LOAD((i + 3) & 3, k0 + 48);
    int s = i & 3;
#pragma unroll
    for (int ks = 0; ks < 16; ks += 8) {
      uint32_t af[2][4], bf[2][2];
#pragma unroll
      for (int t = 0; t < 2; t++) {
        int row = wm + t * 16 + gid;
        af[t][0] = __float_as_uint(As[s][row][ks + tig]);
        af[t][1] = __float_as_uint(As[s][row + 8][ks + tig]);
        af[t][2] = __float_as_uint(As[s][row][ks + tig + 4]);
        af[t][3] = __float_as_uint(As[s][row + 8][ks + tig + 4]);
      }
#pragma unroll
      for (int u = 0; u < 2; u++) {
        int col = wn + u * 8 + gid;
        bf[u][0] = __float_as_uint(Bs[s][ks + tig][col]);
        bf[u][1] = __float_as_uint(Bs[s][ks + tig + 4][col]);
      }
#pragma unroll
      for (int t = 0; t < 2; t++)
#pragma unroll
        for (int u = 0; u < 2; u++) mma_tf32(acc[t][u], af[t], bf[u]);
    }
  }
#undef GEMM_LOAD

#pragma unroll
  for (int t = 0; t < 2; t++) {
#pragma unroll
    for (int u = 0; u < 2; u++) {
      int r = bm + wm + t * 16 + gid;
      int c = bn + wn + u * 8 + tig * 2;
      float b0 = bias ? bias[c] : 0.f;
      float b1 = bias ? bias[c + 1] : 0.f;
      float2 o0 = {acc[t][u][0] + b0, acc[t][u][1] + b1};
      float2 o1 = {acc[t][u][2] + b0, acc[t][u][3] + b1};
      if (RELU) {
        o0.x = fmaxf(o0.x, 0.f); o0.y = fmaxf(o0.y, 0.f);
        o1.x = fmaxf(o1.x, 0.f); o1.y = fmaxf(o1.y, 0.f);
      }
      *(float2*)(C + (size_t)r * Nn + c) = o0;
      *(float2*)(C + (size_t)(r + 8) * Nn + c) = o1;
    }
  }
}

// ---------------- TF32 tensor-core flash attention ----------------
// grid (N/64, H), block 128 (4 warps x 16 q-rows). Tiles: 64q x 64k, DH=32.
// K double-buffered via cp.async; V single-buffered, prefetched post-PV.
// Conflict-free strides mod 32: Ks 36->4, Vs 40->8, Ps 68->4.
__global__ __launch_bounds__(128) void attn_mma() {
  __shared__ float Ks[2][64][36];
  __shared__ float Vs[64][40];
  __shared__ float Ps[64][68];
  int tid = threadIdx.x;
  int warp = tid >> 5, lane = tid & 31;
  int gid = lane >> 2, tig = lane & 3;
  int h = blockIdx.y;
  int qb = blockIdx.x * 64;
  int r0 = warp * 16 + gid;
  const float scale = 0.17677669529663687f;  // 1/sqrt(32)

#define K_LOAD(s, kt)                                                     \
  do {                                                                    \
    _Pragma("unroll") for (int j = 0; j < 4; j++) {                       \
      int idx = tid + j * 128;                                            \
      int r = idx >> 3, c4 = (idx & 7) * 4;                               \
      cp_async16(&Ks[s][r][c4],                                           \
                 g_qkv + (size_t)((kt) + r) * 768 + 256 + h * 32 + c4);   \
    }                                                                     \
    cp_commit();                                                          \
  } while (0)
#define V_LOAD(kt)                                                        \
  do {                                                                    \
    _Pragma("unroll") for (int j = 0; j < 4; j++) {                       \
      int idx = tid + j * 128;                                            \
      int r = idx >> 3, c4 = (idx & 7) * 4;                               \
      cp_async16(&Vs[r][c4],                                              \
                 g_qkv + (size_t)((kt) + r) * 768 + 512 + h * 32 + c4);   \
    }                                                                     \
    cp_commit();                                                          \
  } while (0)

  K_LOAD(0, 0);
  V_LOAD(0);
  K_LOAD(1, 64);

  // ---- stage scaled Q tile (64x32) through Ps, build fragments
#pragma unroll
  for (int j = 0; j < 4; j++) {
    int idx = tid + j * 128;
    int r = idx >> 3, c4 = (idx & 7) * 4;
    float4 v = *(const float4*)(g_qkv + (size_t)(qb + r) * 768 + h * 32 + c4);
    Ps[r][c4 + 0] = v.x * scale;
    Ps[r][c4 + 1] = v.y * scale;
    Ps[r][c4 + 2] = v.z * scale;
    Ps[r][c4 + 3] = v.w * scale;
  }
  __syncthreads();
  uint32_t qf[4][4];
#pragma unroll
  for (int ks = 0; ks < 4; ks++) {
    qf[ks][0] = __float_as_uint(Ps[r0][ks * 8 + tig]);
    qf[ks][1] = __float_as_uint(Ps[r0 + 8][ks * 8 + tig]);
    qf[ks][2] = __float_as_uint(Ps[r0][ks * 8 + tig + 4]);
    qf[ks][3] = __float_as_uint(Ps[r0 + 8][ks * 8 + tig + 4]);
  }
  __syncthreads();

  float m0 = -1e30f, m1 = -1e30f, Z0 = 0.f, Z1 = 0.f;
  float oacc[4][4];
#pragma unroll
  for (int u = 0; u < 4; u++)
#pragma unroll
    for (int i = 0; i < 4; i++) oacc[u][i] = 0.f;

  int s = 0;
  for (int kt = 0; kt < N_NODES; kt += 64) {
    if (kt + 64 < N_NODES) cp_wait<1>();
    else cp_wait<0>();
    __syncthreads();

    float sc[8][4];
#pragma unroll
    for (int u = 0; u < 8; u++) {
      sc[u][0] = sc[u][1] = sc[u][2] = sc[u][3] = 0.f;
#pragma unroll
      for (int ks = 0; ks < 4; ks++) {
        uint32_t bf[2];
        bf[0] = __float_as_uint(Ks[s][u * 8 + gid][ks * 8 + tig]);
        bf[1] = __float_as_uint(Ks[s][u * 8 + gid][ks * 8 + tig + 4]);
        mma_tf32(sc[u], qf[ks], bf);
      }
    }
    float t0 = -1e30f, t1 = -1e30f;
#pragma unroll
    for (int u = 0; u < 8; u++) {
      t0 = fmaxf(t0, fmaxf(sc[u][0], sc[u][1]));
      t1 = fmaxf(t1, fmaxf(sc[u][2], sc[u][3]));
    }
#pragma unroll
    for (int o = 1; o < 4; o <<= 1) {
      t0 = fmaxf(t0, __shfl_xor_sync(0xffffffffu, t0, o));
      t1 = fmaxf(t1, __shfl_xor_sync(0xffffffffu, t1, o));
    }
    float mn0 = fmaxf(m0, t0), mn1 = fmaxf(m1, t1);
    float f0 = __expf(m0 - mn0), f1 = __expf(m1 - mn1);
    m0 = mn0; m1 = mn1;
    float l0 = 0.f, l1 = 0.f;
#pragma unroll
    for (int u = 0; u < 8; u++) {
      float p00 = __expf(sc[u][0] - mn0);
      float p01 = __expf(sc[u][1] - mn0);
      float p10 = __expf(sc[u][2] - mn1);
      float p11 = __expf(sc[u][3] - mn1);
      l0 += p00 + p01; l1 += p10 + p11;
      float2 w0 = {p00, p01};
      float2 w1 = {p10, p11};
      *(float2*)&Ps[r0][u * 8 + tig * 2] = w0;
      *(float2*)&Ps[r0 + 8][u * 8 + tig * 2] = w1;
    }
#pragma unroll
    for (int o = 1; o < 4; o <<= 1) {
      l0 += __shfl_xor_sync(0xffffffffu, l0, o);
      l1 += __shfl_xor_sync(0xffffffffu, l1, o);
    }
    Z0 = Z0 * f0 + l0;
    Z1 = Z1 * f1 + l1;
#pragma unroll
    for (int u = 0; u < 4; u++) {
      oacc[u][0] *= f0; oacc[u][1] *= f0;
      oacc[u][2] *= f1; oacc[u][3] *= f1;
    }
    __syncwarp();

#pragma unroll
    for (int ks = 0; ks < 8; ks++) {
      uint32_t af[4];
      af[0] = __float_as_uint(Ps[r0][ks * 8 + tig]);
      af[1] = __float_as_uint(Ps[r0 + 8][ks * 8 + tig]);
      af[2] = __float_as_uint(Ps[r0][ks * 8 + tig + 4]);
      af[3] = __float_as_uint(Ps[r0 + 8][ks * 8 + tig + 4]);
#pragma unroll
      for (int u = 0; u < 4; u++) {
        uint32_t bf[2];
        bf[0] = __float_as_uint(Vs[ks * 8 + tig][u * 8 + gid]);
        bf[1] = __float_as_uint(Vs[ks * 8 + tig + 4][u * 8 + gid]);
        mma_tf32(oacc[u], af, bf);
      }
    }
    __syncthreads();
    if (kt + 64 < N_NODES) V_LOAD(kt + 64);
    if (kt + 128 < N_NODES) K_LOAD(s, kt + 128);
    s ^= 1;
  }
#undef K_LOAD
#undef V_LOAD

  float i0 = 1.f / Z0, i1 = 1.f / Z1;
#pragma unroll
  for (int u = 0; u < 4; u++) {
    float2 o0 = {oacc[u][0] * i0, oacc[u][1] * i0};
    float2 o1 = {oacc[u][2] * i1, oacc[u][3] * i1};
    int c = h * 32 + u * 8 + tig * 2;
    *(float2*)(g_ctx + (size_t)(qb + r0) * 256 + c) = o0;
    *(float2*)(g_ctx + (size_t)(qb + r0 + 8) * 256 + c) = o1;
  }
}

// ---------------- residual + LayerNorm ----------------
__global__ __launch_bounds__(256) void ln_res(const float* __restrict__ a,
                                              const float* __restrict__ b,
                                              const float* __restrict__ gam,
                                              const float* __restrict__ bet,
                                              float* __restrict__ out) {
  int w = threadIdx.x >> 5, lane = threadIdx.x & 31;
  int row = blockIdx.x * 8 + w;
  float x[8];
  float s = 0.f;
#pragma unroll
  for (int i = 0; i < 8; i++) {
    int d = lane + i * 32;
    x[i] = a[(size_t)row * 256 + d] + b[(size_t)row * 256 + d];
    s += x[i];
  }
#pragma unroll
  for (int o = 16; o; o >>= 1) s += __shfl_xor_sync(0xffffffffu, s, o);
  float mean = s * (1.f / 256.f);
  float v = 0.f;
#pragma unroll
  for (int i = 0; i < 8; i++) {
    float t = x[i] - mean;
    v += t * t;
  }
#pragma unroll
  for (int o = 16; o; o >>= 1) v += __shfl_xor_sync(0xffffffffu, v, o);
  float r = rsqrtf(v * (1.f / 256.f) + 1e-5f);
#pragma unroll
  for (int i = 0; i < 8; i++) {
    int d = lane + i * 32;
    out[(size_t)row * 256 + d] = (x[i] - mean) * r * gam[d] + bet[d];
  }
}

// ---------------- GAT attention dot products ----------------
__global__ __launch_bounds__(256) void gat_dots(const float* __restrict__ att_src,
                                                const float* __restrict__ att_dst) {
  int n = blockIdx.x;
  int w = threadIdx.x >> 5, lane = threadIdx.x & 31;
  const float* row = g_hw + (size_t)n * 2048 + w * 256;
  float s1 = 0.f, s2 = 0.f;
#pragma unroll
  for (int i = 0; i < 8; i++) {
    int d = lane + i * 32;
    float v = row[d];
    s1 += v * att_src[w * 256 + d];
    s2 += v * att_dst[w * 256 + d];
  }
#pragma unroll
  for (int o = 16; o; o >>= 1) {
    s1 += __shfl_xor_sync(0xffffffffu, s1, o);
    s2 += __shfl_xor_sync(0xffffffffu, s2, o);
  }
  if (!lane) {
    g_asrc[n * 8 + w] = s1;
    g_adst[n * 8 + w] = s2;
  }
}

// ---------------- CSR build ----------------
__global__ void csr_zero() {
  int i = blockIdx.x * 256 + threadIdx.x;
  if (i < N_NODES) g_deg[i] = 0;
}
__global__ void csr_count(const int* __restrict__ ei) {
  int i = blockIdx.x * 256 + threadIdx.x;
  if (i >= EN_EDGES) return;
  int d = (i < E_EDGES) ? ei[E_EDGES + i] : (i - E_EDGES);
  atomicAdd(&g_deg[d], 1);
}
__global__ __launch_bounds__(1024) void csr_scan() {
  __shared__ int s[1024];
  int tid = threadIdx.x;
  int v0 = g_deg[tid * 4 + 0], v1 = g_deg[tid * 4 + 1];
  int v2 = g_deg[tid * 4 + 2], v3 = g_deg[tid * 4 + 3];
  int tsum = v0 + v1 + v2 + v3;
  s[tid] = tsum;
  __syncthreads();
  for (int o = 1; o < 1024; o <<= 1) {
    int t = (tid >= o) ? s[tid - o] : 0;
    __syncthreads();
    s[tid] += t;
    __syncthreads();
  }
  int excl = tid ? s[tid - 1] : 0;
  int o0 = excl, o1 = o0 + v0, o2 = o1 + v1, o3 = o2 + v2;
  g_off[tid * 4 + 0] = o0; g_cursor[tid * 4 + 0] = o0;
  g_off[tid * 4 + 1] = o1; g_cursor[tid * 4 + 1] = o1;
  g_off[tid * 4 + 2] = o2; g_cursor[tid * 4 + 2] = o2;
  g_off[tid * 4 + 3] = o3; g_cursor[tid * 4 + 3] = o3;
  if (tid == 1023) g_off[N_NODES] = excl + tsum;
}
__global__ void csr_fill(const int* __restrict__ ei) {
  int i = blockIdx.x * 256 + threadIdx.x;
  if (i >= EN_EDGES) return;
  int srcv = (i < E_EDGES) ? ei[i] : (i - E_EDGES);
  int dstv = (i < E_EDGES) ? ei[E_EDGES + i] : (i - E_EDGES);
  int pos = atomicAdd(&g_cursor[dstv], 1);
  g_csrc[pos] = srcv;
}

// ---------------- GAT aggregation ----------------
__global__ __launch_bounds__(256) void gat_agg(const float* __restrict__ gat_bias) {
  int n = blockIdx.x, tid = threadIdx.x;
  __shared__ int ssrc[256];
  __shared__ float se[256 * 8];
  __shared__ float sm[8], sz[8], sfac[8], sadst[8];
  __shared__ float sred[8 * 32];

  int start = g_off[n], end = g_off[n + 1];
  if (tid < 8) {
    sm[tid] = -1e30f;
    sz[tid] = 0.f;
    sadst[tid] = g_adst[n * 8 + tid];
  }
  float acc[8];
#pragma unroll
  for (int i = 0; i < 8; i++) acc[i] = 0.f;
  __syncthreads();

  for (int cs = start; cs < end; cs += 256) {
    int cnt = min(256, end - cs);
    if (tid < cnt) ssrc[tid] = g_csrc[cs + tid];
    __syncthreads();
#pragma unroll
    for (int j = 0; j < 8; j++) {
      int idx = tid + j * 256;
      int eidx = idx >> 3, hh = idx & 7;
      if (eidx < cnt) {
        float v = g_asrc[ssrc[eidx] * 8 + hh] + sadst[hh];
        se[idx] = (v > 0.f) ? v : 0.2f * v;
      }
    }
    __syncthreads();
    int h = tid & 7, gg = tid >> 3;
    float mx = -1e30f;
    for (int e = gg; e < cnt; e += 32) mx = fmaxf(mx, se[e * 8 + h]);
    sred[h * 32 + gg] = mx;
    __syncthreads();
    if (tid < 8) {
      float m2 = -1e30f;
      for (int g2 = 0; g2 < 32; g2++) m2 = fmaxf(m2, sred[tid * 32 + g2]);
      float mold = sm[tid];
      float mnew = fmaxf(mold, m2);
      sfac[tid] = __expf(mold - mnew);
      sm[tid] = mnew;
      sz[tid] *= sfac[tid];
    }
    __syncthreads();
#pragma unroll
    for (int i = 0; i < 8; i++) acc[i] *= sfac[i];
    float sum = 0.f;
    for (int e = gg; e < cnt; e += 32) {
      float p = __expf(se[e * 8 + h] - sm[h]);
      se[e * 8 + h] = p;
      sum += p;
    }
    sred[h * 32 + gg] = sum;
    __syncthreads();
    if (tid < 8) {
      float s2 = 0.f;
      for (int g2 = 0; g2 < 32; g2++) s2 += sred[tid * 32 + g2];
      sz[tid] += s2;
    }
    __syncthreads();
    // accumulate, unrolled x2 for memory-level parallelism
    int e2 = cnt & ~1;
    for (int e = 0; e < e2; e += 2) {
      const float* ra = g_hw + (size_t)ssrc[e] * 2048 + tid;
      const float* rb = g_hw + (size_t)ssrc[e + 1] * 2048 + tid;
      float va[8], vb[8];
#pragma unroll
      for (int hh = 0; hh < 8; hh++) {
        va[hh] = ra[hh * 256];
        vb[hh] = rb[hh * 256];
      }
#pragma unroll
      for (int hh = 0; hh < 8; hh++)
        acc[hh] += se[e * 8 + hh] * va[hh] + se[e * 8 + 8 + hh] * vb[hh];
    }
    if (e2 < cnt) {
      const float* ra = g_hw + (size_t)ssrc[e2] * 2048 + tid;
#pragma unroll
      for (int hh = 0; hh < 8; hh++)
        acc[hh] += se[e2 * 8 + hh] * ra[hh * 256];
    }
    __syncthreads();
  }
  float r = 0.f;
#pragma unroll
  for (int hh = 0; hh < 8; hh++) r += acc[hh] / (sz[hh] + 1e-16f);
  g_hg[(size_t)n * 256 + tid] = r * 0.125f + gat_bias[tid];
}

// ---------------- fused classifier ----------------
__global__ __launch_bounds__(256) void classify(
    const float* __restrict__ w1, const float* __restrict__ b1,
    const float* __restrict__ w2, const float* __restrict__ b2,
    const int* __restrict__ iA, const int* __restrict__ iB,
    float* __restrict__ out) {
  __shared__ float sp[16][512];
  __shared__ int sia[16], sib[16];
  int tid = threadIdx.x;
  int bp = blockIdx.x * 16;
  if (tid < 16) sia[tid] = iA[bp + tid];
  else if (tid < 32) sib[tid - 16] = iB[bp + tid - 16];
  __syncthreads();
#pragma unroll
  for (int j = 0; j < 8; j++) {
    int idx4 = tid + j * 256;
    int p = idx4 >> 7;
    int c = (idx4 & 127) * 4;
    const float* src = (c < 256) ? (g_hg + (size_t)sia[p] * 256 + c)
                                 : (g_hg + (size_t)sib[p] * 256 + (c - 256));
    *(float4*)&sp[p][c] = *(const float4*)src;
  }
  __syncthreads();
  int p = tid >> 4;
  int j0 = (tid & 15) * 4;
  float a0 = 0.f, a1 = 0.f, a2 = 0.f, a3 = 0.f;
  for (int k = 0; k < 512; k++) {
    float s = sp[p][k];
    float4 w = *(const float4*)(w1 + (size_t)k * 64 + j0);
    a0 += s * w.x; a1 += s * w.y; a2 += s * w.z; a3 += s * w.w;
  }
  a0 = fmaxf(a0 + b1[j0 + 0], 0.f);
  a1 = fmaxf(a1 + b1[j0 + 1], 0.f);
  a2 = fmaxf(a2 + b1[j0 + 2], 0.f);
  a3 = fmaxf(a3 + b1[j0 + 3], 0.f);
  float part = a0 * w2[j0 + 0] + a1 * w2[j0 + 1] + a2 * w2[j0 + 2] + a3 * w2[j0 + 3];
#pragma unroll
  for (int o = 1; o < 16; o <<= 1) part += __shfl_xor_sync(0xffffffffu, part, o);
  if ((tid & 15) == 0) {
    float z = part + b2[0];
    out[bp + p] = 1.f / (1.f + __expf(-z));
  }
}

// ---------------- launch ----------------
extern "C" void kernel_launch(void* const* d_in, const int* in_sizes, int n_in,
                              void* d_out, int out_size) {
  const float* x = (const float*)d_in[0];
  const int* edge_index = (const int*)d_in[1];
  const int* idx_A = (const int*)d_in[2];
  const int* idx_B = (const int*)d_in[3];
  const float* w_in = (const float*)d_in[4];
  const float* b_in = (const float*)d_in[5];
  const float* w_qkv = (const float*)d_in[6];
  const float* b_qkv = (const float*)d_in[7];
  const float* w_o = (const float*)d_in[8];
  const float* b_o = (const float*)d_in[9];
  const float* ln1_g = (const float*)d_in[10];
  const float* ln1_b = (const float*)d_in[11];
  const float* w_ff1 = (const float*)d_in[12];
  const float* b_ff1 = (const float*)d_in[13];
  const float* w_ff2 = (const float*)d_in[14];
  const float* b_ff2 = (const float*)d_in[15];
  const float* ln2_g = (const float*)d_in[16];
  const float* ln2_b = (const float*)d_in[17];
  const float* gat_w = (const float*)d_in[18];
  const float* att_src = (const float*)d_in[19];
  const float* att_dst = (const float*)d_in[20];
  const float* gat_bias = (const float*)d_in[21];
  const float* cls_w1 = (const float*)d_in[22];
  const float* cls_b1 = (const float*)d_in[23];
  const float* cls_w2 = (const float*)d_in[24];
  const float* cls_b2 = (const float*)d_in[25];
  float* out = (float*)d_out;

  void* p;
  cudaGetSymbolAddress(&p, g_h);   float* ph = (float*)p;
  cudaGetSymbolAddress(&p, g_qkv); float* pqkv = (float*)p;
  cudaGetSymbolAddress(&p, g_ctx); float* pctx = (float*)p;
  cudaGetSymbolAddress(&p, g_tmp); float* ptmp = (float*)p;
  cudaGetSymbolAddress(&p, g_h1);  float* ph1 = (float*)p;
  cudaGetSymbolAddress(&p, g_ff);  float* pff = (float*)p;
  cudaGetSymbolAddress(&p, g_h2);  float* ph2 = (float*)p;
  cudaGetSymbolAddress(&p, g_hw);  float* phw = (float*)p;

  mma_gemm<0><<<dim3(D_MODEL / 64, N_NODES / 64), 256>>>(
      x, w_in, b_in, ph, N_NODES, D_MODEL, D_INP);
  mma_gemm<0><<<dim3(3 * D_MODEL / 64, N_NODES / 64), 256>>>(
      ph, w_qkv, b_qkv, pqkv, N_NODES, 3 * D_MODEL, D_MODEL);
  attn_mma<<<dim3(N_NODES / 64, H_HEADS), 128>>>();
  mma_gemm<0><<<dim3(D_MODEL / 64, N_NODES / 64), 256>>>(
      pctx, w_o, b_o, ptmp, N_NODES, D_MODEL, D_MODEL);
  ln_res<<<N_NODES / 8, 256>>>(ph, ptmp, ln1_g, ln1_b, ph1);
  mma_gemm<1><<<dim3(FF_DIM / 64, N_NODES / 64), 256>>>(
      ph1, w_ff1, b_ff1, pff, N_NODES, FF_DIM, D_MODEL);
  mma_gemm<0><<<dim3(D_MODEL / 64, N_NODES / 64), 256>>>(
      pff, w_ff2, b_ff2, ptmp, N_NODES, D_MODEL, FF_DIM);
  ln_res<<<N_NODES / 8, 256>>>(ph1, ptmp, ln2_g, ln2_b, ph2);
  mma_gemm<0><<<dim3(H_HEADS * D_MODEL / 64, N_NODES / 64), 256>>>(
      ph2, gat_w, (const float*)nullptr, phw, N_NODES, H_HEADS * D_MODEL,
      D_MODEL);
  gat_dots<<<N_NODES, 256>>>(att_src, att_dst);
  csr_zero<<<(N_NODES + 255) / 256, 256>>>();
  csr_count<<<(EN_EDGES + 255) / 256, 256>>>(edge_index);
  csr_scan<<<1, 1024>>>();
  csr_fill<<<(EN_EDGES + 255) / 256, 256>>>(edge_index);
  gat_agg<<<N_NODES, 256>>>(gat_bias);
  classify<<<B_PAIRS / 16, 256>>>(cls_w1, cls_b1, cls_w2, cls_b2, idx_A, idx_B,
                                  out);
}